// round 3
// baseline (speedup 1.0000x reference)
#include <cuda_runtime.h>
#include <cuda_bf16.h>
#include <cstdint>

#define T_ 4
#define B_ 8
#define C_ 512
#define D_ 768
#define H_ 8
#define HD_ 96
#define MKV_ 192
#define NCAT_ 1152            // 768 (q) + 192 (k) + 192 (v)
#define BC_ 4096              // B*C
#define M_ 16384              // T*B*C
#define BCD_ 3145728          // B*C*D

// ---------------- scratch (device globals: no allocation allowed) ----------
__device__ __nv_bfloat16 g_xs[M_ * D_];        // proj_lif spikes (exact 0/1)
__device__ __nv_bfloat16 g_Whi[NCAT_ * D_];    // concat [q_w; k_w; v_w] hi
__device__ __nv_bfloat16 g_Wlo[NCAT_ * D_];    // lo residual
__device__ __nv_bfloat16 g_WOhi[D_ * D_];
__device__ __nv_bfloat16 g_WOlo[D_ * D_];
__device__ int8_t        g_sp8[M_ * NCAT_];    // q/k/v spikes (int8 0/1)
__device__ int8_t        g_vT8[T_ * B_ * MKV_ * C_]; // v spikes transposed
__device__ __nv_bfloat16 g_ahi[M_ * D_];       // attention output hi
__device__ __nv_bfloat16 g_alo[M_ * D_];       // attention output lo

// ================= helpers =================
__device__ __forceinline__ uint32_t smem_u32(const void* p) {
    uint32_t a;
    asm("{ .reg .u64 t; cvta.to.shared.u64 t, %1; cvt.u32.u64 %0, t; }" : "=r"(a) : "l"(p));
    return a;
}
#define CP_ASYNC16(dst, src) \
    asm volatile("cp.async.cg.shared.global [%0], [%1], 16;" :: "r"(dst), "l"(src))
#define CP_COMMIT()  asm volatile("cp.async.commit_group;" ::: "memory")
#define CP_WAIT(n)   asm volatile("cp.async.wait_group %0;" :: "n"(n) : "memory")

__device__ __forceinline__ void mma_bf16(float* c, const uint32_t* a, const uint32_t* b) {
    asm volatile(
        "mma.sync.aligned.m16n8k16.row.col.f32.bf16.bf16.f32 "
        "{%0,%1,%2,%3},{%4,%5,%6,%7},{%8,%9},{%0,%1,%2,%3};\n"
        : "+f"(c[0]), "+f"(c[1]), "+f"(c[2]), "+f"(c[3])
        : "r"(a[0]), "r"(a[1]), "r"(a[2]), "r"(a[3]), "r"(b[0]), "r"(b[1]));
}
__device__ __forceinline__ void mma_s8(int32_t* c, const uint32_t* a, const uint32_t* b) {
    asm volatile(
        "mma.sync.aligned.m16n8k32.row.col.s32.s8.s8.s32 "
        "{%0,%1,%2,%3},{%4,%5,%6,%7},{%8,%9},{%0,%1,%2,%3};\n"
        : "+r"(c[0]), "+r"(c[1]), "+r"(c[2]), "+r"(c[3])
        : "r"(a[0]), "r"(a[1]), "r"(a[2]), "r"(a[3]), "r"(b[0]), "r"(b[1]));
}

// ---------------- kernel 1: split weights into bf16 hi/lo ----------------
__global__ void pack_w_k(const float* __restrict__ qw, const float* __restrict__ kw,
                         const float* __restrict__ vw, const float* __restrict__ wow) {
    int i = blockIdx.x * 256 + threadIdx.x;
    if (i < NCAT_ * D_) {
        int n = i / D_, k = i - n * D_;
        float w;
        if (n < D_)            w = qw[i];
        else if (n < D_ + MKV_) w = kw[(n - D_) * D_ + k];
        else                    w = vw[(n - D_ - MKV_) * D_ + k];
        __nv_bfloat16 hi = __float2bfloat16(w);
        g_Whi[i] = hi;
        g_Wlo[i] = __float2bfloat16(w - __bfloat162float(hi));
    }
    if (i < D_ * D_) {
        float w = wow[i];
        __nv_bfloat16 hi = __float2bfloat16(w);
        g_WOhi[i] = hi;
        g_WOlo[i] = __float2bfloat16(w - __bfloat162float(hi));
    }
}

// ---------------- kernel 2: LIF on x -> xs spikes (bf16 exact) -------------
__global__ void lif_x_k(const float* __restrict__ x) {
    int i = blockIdx.x * 256 + threadIdx.x;
    if (i >= BCD_) return;
    float v = 0.f;
#pragma unroll
    for (int t = 0; t < T_; t++) {
        v = v * 0.5f + x[t * BCD_ + i];
        bool s = (v >= 1.0f);
        g_xs[t * BCD_ + i] = __float2bfloat16(s ? 1.f : 0.f);
        if (s) v = 0.f;
    }
}

// ====== kernel 3: fused projection GEMM + LIF =============================
// For fixed (bc-block m0, n-block n0): loop t=0..3, full K GEMM
// pre = xs_t @ W^T (hi+lo), then LIF update (v state in smem), emit int8 spikes.
#define SROW 144                    // smem row stride bytes (64 bf16 + pad)
#define TILE_B (128 * SROW)         // 18432
#define STAGE_B (3 * TILE_B)        // A, Bh, Bl
#define VOFF (2 * STAGE_B)          // membrane state offset
#define NCHUNK 12                   // K=768 / 64
__global__ void __launch_bounds__(256)
gemm_proj_fused() {
    extern __shared__ char sm[];
    uint32_t sb = smem_u32(sm);
    float* vsm = (float*)(sm + VOFF);   // [64 slots][256 threads]

    int tid = threadIdx.x;
    int lane = tid & 31, warp = tid >> 5;
    int gid = lane >> 2, tig = lane & 3;
    int wm = (warp >> 2) * 64, wn = (warp & 3) * 32;
    int m0 = blockIdx.y * 128, n0 = blockIdx.x * 128;

#pragma unroll
    for (int s = 0; s < 64; s++) vsm[s * 256 + tid] = 0.f;
    __syncthreads();

    int ldr = tid >> 3, ldc = (tid & 7) * 16;   // row, byte-col for cp.async (half rows/iter)

    for (int t = 0; t < T_; t++) {
        float acc[4][4][4];
#pragma unroll
        for (int a = 0; a < 4; a++)
#pragma unroll
            for (int b = 0; b < 4; b++)
#pragma unroll
                for (int c = 0; c < 4; c++) acc[a][b][c] = 0.f;

        // prologue: chunk 0 -> stage 0
#pragma unroll
        for (int it = 0; it < 4; it++) {
            int r = ldr + it * 32;
            CP_ASYNC16(sb + r * SROW + ldc,
                       (const char*)(g_xs + (size_t)(t * BC_ + m0 + r) * D_) + ldc);
            CP_ASYNC16(sb + TILE_B + r * SROW + ldc,
                       (const char*)(g_Whi + (size_t)(n0 + r) * D_) + ldc);
            CP_ASYNC16(sb + 2 * TILE_B + r * SROW + ldc,
                       (const char*)(g_Wlo + (size_t)(n0 + r) * D_) + ldc);
        }
        CP_COMMIT();

        for (int c = 0; c < NCHUNK; c++) {
            int cur = (c & 1) * STAGE_B;
            if (c + 1 < NCHUNK) {
                int nxt = ((c + 1) & 1) * STAGE_B;
                int kb = (c + 1) * 128;  // byte offset in K (64 bf16)
#pragma unroll
                for (int it = 0; it < 4; it++) {
                    int r = ldr + it * 32;
                    CP_ASYNC16(sb + nxt + r * SROW + ldc,
                               (const char*)(g_xs + (size_t)(t * BC_ + m0 + r) * D_) + kb + ldc);
                    CP_ASYNC16(sb + nxt + TILE_B + r * SROW + ldc,
                               (const char*)(g_Whi + (size_t)(n0 + r) * D_) + kb + ldc);
                    CP_ASYNC16(sb + nxt + 2 * TILE_B + r * SROW + ldc,
                               (const char*)(g_Wlo + (size_t)(n0 + r) * D_) + kb + ldc);
                }
                CP_COMMIT();
                CP_WAIT(1);
            } else {
                CP_WAIT(0);
            }
            __syncthreads();
            const char* sA = sm + cur;
            const char* sBh = sm + cur + TILE_B;
            const char* sBl = sm + cur + 2 * TILE_B;
#pragma unroll
            for (int kk = 0; kk < 4; kk++) {
                int kb = kk * 32 + tig * 4;
                uint32_t af[4][4];
#pragma unroll
                for (int mt = 0; mt < 4; mt++) {
                    int r = wm + mt * 16 + gid;
                    af[mt][0] = *(const uint32_t*)(sA + r * SROW + kb);
                    af[mt][1] = *(const uint32_t*)(sA + (r + 8) * SROW + kb);
                    af[mt][2] = *(const uint32_t*)(sA + r * SROW + kb + 16);
                    af[mt][3] = *(const uint32_t*)(sA + (r + 8) * SROW + kb + 16);
                }
#pragma unroll
                for (int nt = 0; nt < 4; nt++) {
                    int nb = wn + nt * 8 + gid;
                    uint32_t bh[2], bl[2];
                    bh[0] = *(const uint32_t*)(sBh + nb * SROW + kb);
                    bh[1] = *(const uint32_t*)(sBh + nb * SROW + kb + 16);
                    bl[0] = *(const uint32_t*)(sBl + nb * SROW + kb);
                    bl[1] = *(const uint32_t*)(sBl + nb * SROW + kb + 16);
#pragma unroll
                    for (int mt = 0; mt < 4; mt++) {
                        mma_bf16(acc[mt][nt], af[mt], bh);
                        mma_bf16(acc[mt][nt], af[mt], bl);
                    }
                }
            }
            __syncthreads();
        }

        // LIF epilogue for this t
#pragma unroll
        for (int mt = 0; mt < 4; mt++)
#pragma unroll
            for (int nt = 0; nt < 4; nt++) {
                int slot = (mt * 4 + nt) * 4;
                uint8_t s[4];
#pragma unroll
                for (int i = 0; i < 4; i++) {
                    float v = vsm[(slot + i) * 256 + tid];
                    v = v * 0.5f + acc[mt][nt][i];
                    bool sp = (v >= 1.0f);
                    s[i] = sp ? 1 : 0;
                    vsm[(slot + i) * 256 + tid] = sp ? 0.f : v;
                }
                size_t grow = (size_t)(t * BC_ + m0 + wm + mt * 16 + gid);
                int col = n0 + wn + nt * 8 + tig * 2;
                *(uint16_t*)(g_sp8 + grow * NCAT_ + col) =
                    (uint16_t)(s[0] | (s[1] << 8));
                *(uint16_t*)(g_sp8 + (grow + 8) * NCAT_ + col) =
                    (uint16_t)(s[2] | (s[3] << 8));
            }
    }
}

// ---------------- kernel 4: transpose v spikes (coalesced tiles) -----------
__global__ void transpose_v_k() {
    __shared__ int8_t smT[32][33];
    int c0 = blockIdx.x * 32, n0 = blockIdx.y * 32, z = blockIdx.z; // z = t*B+b
    int t = z >> 3, b = z & 7;
    int tx = threadIdx.x, ty = threadIdx.y;
#pragma unroll
    for (int j = 0; j < 4; j++) {
        int r = ty + j * 8;
        smT[r][tx] = g_sp8[(size_t)(t * BC_ + b * C_ + c0 + r) * NCAT_ + (D_ + MKV_) + n0 + tx];
    }
    __syncthreads();
#pragma unroll
    for (int j = 0; j < 4; j++) {
        int nv = ty + j * 8;
        g_vT8[((size_t)z * MKV_ + n0 + nv) * C_ + c0 + tx] = smT[tx][nv];
    }
}

// ---------------- kernel 5: int8 attention  out = 0.1 * (q k^T) v  (exact) -
#define QST 112   // int8 row stride for 96-col tiles
#define SST 144   // int8 row stride for 128-col tiles
__global__ void __launch_bounds__(256)
attn_k() {
    extern __shared__ char smA[];
    char* sQ = smA;                     // 128 x QST
    char* sK = sQ + 128 * QST;          // 128 x QST
    char* sVT = sK + 128 * QST;         // 96 x SST  (v^T: d-major)
    char* sS = sVT + 96 * SST;          // 128 x SST (counts int8, exact)

    int tid = threadIdx.x, lane = tid & 31, warp = tid >> 5;
    int gid = lane >> 2, tig = lane & 3;
    int wm = (warp >> 2) * 64;
    int wn1 = (warp & 3) * 32;
    int wn2 = (warp & 3) * 24;
    int qb = blockIdx.x;
    int tbh = blockIdx.y;
    int h = tbh & 7, tb = tbh >> 3;
    int kvh = h >> 2;
    int qcol = h * HD_;
    int kcol = D_ + kvh * HD_;
    int rowbase = tb * C_;

    // load Q tile 128 x 96 (int8)
#pragma unroll
    for (int it = 0; it < 3; it++) {
        int idx = tid + it * 256;
        int r = idx / 6, c4 = idx % 6;
        *(uint4*)(sQ + r * QST + c4 * 16) =
            *(const uint4*)(g_sp8 + (size_t)(rowbase + qb * 128 + r) * NCAT_ + qcol + c4 * 16);
    }

    int32_t acc2[4][3][4];
#pragma unroll
    for (int a = 0; a < 4; a++)
#pragma unroll
        for (int b = 0; b < 3; b++)
#pragma unroll
            for (int c = 0; c < 4; c++) acc2[a][b][c] = 0;

    for (int kc = 0; kc < 4; kc++) {
#pragma unroll
        for (int it = 0; it < 3; it++) {
            int idx = tid + it * 256;
            int r = idx / 6, c4 = idx % 6;
            *(uint4*)(sK + r * QST + c4 * 16) =
                *(const uint4*)(g_sp8 + (size_t)(rowbase + kc * 128 + r) * NCAT_ + kcol + c4 * 16);
        }
#pragma unroll
        for (int it = 0; it < 3; it++) {
            int idx = tid + it * 256;
            int r = idx >> 3, c8 = idx & 7;
            *(uint4*)(sVT + r * SST + c8 * 16) =
                *(const uint4*)(g_vT8 + (size_t)(tb * MKV_ + kvh * HD_ + r) * C_ + kc * 128 + c8 * 16);
        }
        __syncthreads();

        // mma1: counts = q @ k^T  (128x128, K=96) s8 exact
        int32_t acc1[4][4][4];
#pragma unroll
        for (int a = 0; a < 4; a++)
#pragma unroll
            for (int b = 0; b < 4; b++)
#pragma unroll
                for (int c = 0; c < 4; c++) acc1[a][b][c] = 0;
#pragma unroll
        for (int kk = 0; kk < 3; kk++) {
            int kb = kk * 32 + tig * 4;
            uint32_t af[4][4];
#pragma unroll
            for (int mt = 0; mt < 4; mt++) {
                int r = wm + mt * 16 + gid;
                af[mt][0] = *(const uint32_t*)(sQ + r * QST + kb);
                af[mt][1] = *(const uint32_t*)(sQ + (r + 8) * QST + kb);
                af[mt][2] = *(const uint32_t*)(sQ + r * QST + kb + 16);
                af[mt][3] = *(const uint32_t*)(sQ + (r + 8) * QST + kb + 16);
            }
#pragma unroll
            for (int nt = 0; nt < 4; nt++) {
                int nb = wn1 + nt * 8 + gid;
                uint32_t bb[2];
                bb[0] = *(const uint32_t*)(sK + nb * QST + kb);
                bb[1] = *(const uint32_t*)(sK + nb * QST + kb + 16);
#pragma unroll
                for (int mt = 0; mt < 4; mt++) mma_s8(acc1[mt][nt], af[mt], bb);
            }
        }
        // store counts as int8 (exact, <=96)
#pragma unroll
        for (int mt = 0; mt < 4; mt++)
#pragma unroll
            for (int nt = 0; nt < 4; nt++) {
                int r = wm + mt * 16 + gid;
                int cc = wn1 + nt * 8 + tig * 2;
                *(uint16_t*)(sS + r * SST + cc) =
                    (uint16_t)((acc1[mt][nt][0] & 0xFF) | ((acc1[mt][nt][1] & 0xFF) << 8));
                *(uint16_t*)(sS + (r + 8) * SST + cc) =
                    (uint16_t)((acc1[mt][nt][2] & 0xFF) | ((acc1[mt][nt][3] & 0xFF) << 8));
            }
        __syncthreads();

        // mma2: acc2 += counts @ v  (128x96, K=128) s8 exact
#pragma unroll
        for (int kk = 0; kk < 4; kk++) {
            int kb = kk * 32 + tig * 4;
            uint32_t af[4][4];
#pragma unroll
            for (int mt = 0; mt < 4; mt++) {
                int r = wm + mt * 16 + gid;
                af[mt][0] = *(const uint32_t*)(sS + r * SST + kb);
                af[mt][1] = *(const uint32_t*)(sS + (r + 8) * SST + kb);
                af[mt][2] = *(const uint32_t*)(sS + r * SST + kb + 16);
                af[mt][3] = *(const uint32_t*)(sS + (r + 8) * SST + kb + 16);
            }
#pragma unroll
            for (int nt = 0; nt < 3; nt++) {
                int nb = wn2 + nt * 8 + gid;
                uint32_t bb[2];
                bb[0] = *(const uint32_t*)(sVT + nb * SST + kb);
                bb[1] = *(const uint32_t*)(sVT + nb * SST + kb + 16);
#pragma unroll
                for (int mt = 0; mt < 4; mt++) mma_s8(acc2[mt][nt], af[mt], bb);
            }
        }
        __syncthreads();
    }

    // epilogue: scale by 0.1, hi/lo split for the wo GEMM
#pragma unroll
    for (int mt = 0; mt < 4; mt++)
#pragma unroll
        for (int nt = 0; nt < 3; nt++) {
            int r = rowbase + qb * 128 + wm + mt * 16 + gid;
            int cb = qcol + wn2 + nt * 8 + tig * 2;
#pragma unroll
            for (int half = 0; half < 2; half++) {
                int rr = r + half * 8;
                float v0 = 0.1f * (float)acc2[mt][nt][half * 2 + 0];
                float v1 = 0.1f * (float)acc2[mt][nt][half * 2 + 1];
                __nv_bfloat162 hi2, lo2;
                hi2.x = __float2bfloat16(v0);
                hi2.y = __float2bfloat16(v1);
                lo2.x = __float2bfloat16(v0 - __bfloat162float(hi2.x));
                lo2.y = __float2bfloat16(v1 - __bfloat162float(hi2.y));
                *(__nv_bfloat162*)(g_ahi + (size_t)rr * D_ + cb) = hi2;
                *(__nv_bfloat162*)(g_alo + (size_t)rr * D_ + cb) = lo2;
            }
        }
}

// ====== kernel 6: output GEMM  d_out = attn @ wo^T (bf16 3-pass, piped) ====
#define WSTAGE_B (4 * TILE_B)
__global__ void __launch_bounds__(256)
gemm_wo_k(float* __restrict__ out) {
    extern __shared__ char sm[];
    uint32_t sb = smem_u32(sm);
    int tid = threadIdx.x;
    int lane = tid & 31, warp = tid >> 5;
    int gid = lane >> 2, tig = lane & 3;
    int wm = (warp >> 2) * 64, wn = (warp & 3) * 32;
    int m0 = blockIdx.y * 128, n0 = blockIdx.x * 128;

    float acc[4][4][4];
#pragma unroll
    for (int a = 0; a < 4; a++)
#pragma unroll
        for (int b = 0; b < 4; b++)
#pragma unroll
            for (int c = 0; c < 4; c++) acc[a][b][c] = 0.f;

    int ldr = tid >> 3, ldc = (tid & 7) * 16;

#pragma unroll
    for (int it = 0; it < 4; it++) {
        int r = ldr + it * 32;
        CP_ASYNC16(sb + r * SROW + ldc, (const char*)(g_ahi + (size_t)(m0 + r) * D_) + ldc);
        CP_ASYNC16(sb + TILE_B + r * SROW + ldc, (const char*)(g_alo + (size_t)(m0 + r) * D_) + ldc);
        CP_ASYNC16(sb + 2 * TILE_B + r * SROW + ldc, (const char*)(g_WOhi + (size_t)(n0 + r) * D_) + ldc);
        CP_ASYNC16(sb + 3 * TILE_B + r * SROW + ldc, (const char*)(g_WOlo + (size_t)(n0 + r) * D_) + ldc);
    }
    CP_COMMIT();

    for (int c = 0; c < NCHUNK; c++) {
        int cur = (c & 1) * WSTAGE_B;
        if (c + 1 < NCHUNK) {
            int nxt = ((c + 1) & 1) * WSTAGE_B;
            int kb = (c + 1) * 128;
#pragma unroll
            for (int it = 0; it < 4; it++) {
                int r = ldr + it * 32;
                CP_ASYNC16(sb + nxt + r * SROW + ldc,
                           (const char*)(g_ahi + (size_t)(m0 + r) * D_) + kb + ldc);
                CP_ASYNC16(sb + nxt + TILE_B + r * SROW + ldc,
                           (const char*)(g_alo + (size_t)(m0 + r) * D_) + kb + ldc);
                CP_ASYNC16(sb + nxt + 2 * TILE_B + r * SROW + ldc,
                           (const char*)(g_WOhi + (size_t)(n0 + r) * D_) + kb + ldc);
                CP_ASYNC16(sb + nxt + 3 * TILE_B + r * SROW + ldc,
                           (const char*)(g_WOlo + (size_t)(n0 + r) * D_) + kb + ldc);
            }
            CP_COMMIT();
            CP_WAIT(1);
        } else {
            CP_WAIT(0);
        }
        __syncthreads();
        const char* sAh = sm + cur;
        const char* sAl = sm + cur + TILE_B;
        const char* sBh = sm + cur + 2 * TILE_B;
        const char* sBl = sm + cur + 3 * TILE_B;
#pragma unroll
        for (int kk = 0; kk < 4; kk++) {
            int kb = kk * 32 + tig * 4;
            uint32_t afh[4][4], afl[4][4];
#pragma unroll
            for (int mt = 0; mt < 4; mt++) {
                int r = wm + mt * 16 + gid;
                afh[mt][0] = *(const uint32_t*)(sAh + r * SROW + kb);
                afh[mt][1] = *(const uint32_t*)(sAh + (r + 8) * SROW + kb);
                afh[mt][2] = *(const uint32_t*)(sAh + r * SROW + kb + 16);
                afh[mt][3] = *(const uint32_t*)(sAh + (r + 8) * SROW + kb + 16);
                afl[mt][0] = *(const uint32_t*)(sAl + r * SROW + kb);
                afl[mt][1] = *(const uint32_t*)(sAl + (r + 8) * SROW + kb);
                afl[mt][2] = *(const uint32_t*)(sAl + r * SROW + kb + 16);
                afl[mt][3] = *(const uint32_t*)(sAl + (r + 8) * SROW + kb + 16);
            }
#pragma unroll
            for (int nt = 0; nt < 4; nt++) {
                int nb = wn + nt * 8 + gid;
                uint32_t bh[2], bl[2];
                bh[0] = *(const uint32_t*)(sBh + nb * SROW + kb);
                bh[1] = *(const uint32_t*)(sBh + nb * SROW + kb + 16);
                bl[0] = *(const uint32_t*)(sBl + nb * SROW + kb);
                bl[1] = *(const uint32_t*)(sBl + nb * SROW + kb + 16);
#pragma unroll
                for (int mt = 0; mt < 4; mt++) {
                    mma_bf16(acc[mt][nt], afh[mt], bh);
                    mma_bf16(acc[mt][nt], afh[mt], bl);
                    mma_bf16(acc[mt][nt], afl[mt], bh);
                }
            }
        }
        __syncthreads();
    }
#pragma unroll
    for (int mt = 0; mt < 4; mt++)
#pragma unroll
        for (int nt = 0; nt < 4; nt++) {
            int r = m0 + wm + mt * 16 + gid;
            int cc = n0 + wn + nt * 8 + tig * 2;
            *(float2*)(out + (size_t)r * D_ + cc) = make_float2(acc[mt][nt][0], acc[mt][nt][1]);
            *(float2*)(out + (size_t)(r + 8) * D_ + cc) = make_float2(acc[mt][nt][2], acc[mt][nt][3]);
        }
}

// ---------------- launch ----------------
extern "C" void kernel_launch(void* const* d_in, const int* in_sizes, int n_in,
                              void* d_out, int out_size) {
    (void)in_sizes; (void)n_in; (void)out_size;
    const float* x   = (const float*)d_in[0];
    const float* qw  = (const float*)d_in[1];
    const float* kw  = (const float*)d_in[2];
    const float* vw  = (const float*)d_in[3];
    const float* wow = (const float*)d_in[4];
    float* out = (float*)d_out;

    const int PROJ_SMEM = 2 * STAGE_B + 64 * 256 * 4;   // 110592 + 65536 = 176128
    const int WO_SMEM   = 2 * WSTAGE_B;                 // 147456
    const int ATTN_SMEM = 128 * QST + 128 * QST + 96 * SST + 128 * SST; // 60928
    cudaFuncSetAttribute(gemm_proj_fused, cudaFuncAttributeMaxDynamicSharedMemorySize, PROJ_SMEM);
    cudaFuncSetAttribute(gemm_wo_k, cudaFuncAttributeMaxDynamicSharedMemorySize, WO_SMEM);
    cudaFuncSetAttribute(attn_k, cudaFuncAttributeMaxDynamicSharedMemorySize, ATTN_SMEM);

    pack_w_k<<<(NCAT_ * D_ + 255) / 256, 256>>>(qw, kw, vw, wow);
    lif_x_k<<<(BCD_ + 255) / 256, 256>>>(x);
    gemm_proj_fused<<<dim3(NCAT_ / 128, BC_ / 128), 256, PROJ_SMEM>>>();
    transpose_v_k<<<dim3(C_ / 32, MKV_ / 32, T_ * B_), dim3(32, 8)>>>();
    attn_k<<<dim3(C_ / 128, T_ * B_ * H_), 256, ATTN_SMEM>>>();
    gemm_wo_k<<<dim3(D_ / 128, M_ / 128), 256, WO_SMEM>>>(out);
}